// round 16
// baseline (speedup 1.0000x reference)
#include <cuda_runtime.h>
#include <cstdint>

#define TILE_WORDS 8192
#define NTHREADS   512
#define WPT        (TILE_WORDS / NTHREADS)   // 16 words per thread
#define VECS       (WPT / 4)                 // 4 uint4 per thread
#define NWARPS     (NTHREADS / 32)

// constants from the reference (only the h2 stream reaches the output)
#define FMIX_C1 2246822507u
#define FMIX_C2 3266489909u
#define POS_B   374761393u
#define SEED    608135816u

__device__ __forceinline__ uint32_t fmix32(uint32_t x) {
    x ^= x >> 16; x *= FMIX_C1;
    x ^= x >> 13; x *= FMIX_C2;
    x ^= x >> 16;
    return x;
}

// Fast-path index structure: i = base | (j<<11) | (tid<<2) | k with DISJOINT
// bit fields (base: tile*8192 -> bits 13+; j<4 -> bits 11-12; tid<512 ->
// bits 2-10; k<4 -> bits 0-1). Hence, with X = base + tid*4:
//   rotl(i,13)   = rotl(X,13) | (k<<13) | (j<<24)     (exact, no carries)
//   i*POS_B + s2 = (X*POS_B + s2) + (j*2048+k)*POS_B  (mod 2^32)
// One IMAD + one SHF per THREAD; per word only two IADD3-with-immediate
// (C_jk, D_jk are compile-time constants in the unrolled loops).
// The serial fmix chain stays all-alu (R9/R12: cross-pipe hops regress);
// the accumulate rides the fma pipe via opaque IMAD.
__device__ __forceinline__ void hash_step_c(uint32_t v, uint32_t AX, uint32_t RX,
                                            uint32_t C, uint32_t D,
                                            uint32_t one, uint32_t& acc) {
    uint32_t a2 = AX + C;                         // IADD3 imm (off-chain)
    uint32_t r2 = RX + D;                         // IADD3 imm (off-chain)
    uint32_t x  = fmix32(v ^ a2 ^ r2);            // LOP3 fuses v^a^r
    acc = x * one + acc;                          // IMAD (fma) accumulate
}

__global__ void __launch_bounds__(NTHREADS, 4)
hash_tiles_kernel(const uint32_t* __restrict__ in,
                  float* __restrict__ out,
                  uint32_t n, uint32_t one) {
    const uint32_t tile = blockIdx.x;
    const uint32_t base = tile * TILE_WORDS;
    const uint32_t tid  = threadIdx.x;

    const uint32_t s2 = (uint32_t)((SEED * 2654435761u) ^ 3735928559u);

    uint32_t h2a = 0u, h2b = 0u;   // dual accumulators (wrapping add commutes)

    if (base + TILE_WORDS <= n) {
        // fast path: full tile; 4 coalesced uint4 loads per thread, batched up
        // front (evict-first: single-touch streaming data)
        const uint4* inv = reinterpret_cast<const uint4*>(in + base);
        uint4 v[VECS];
        #pragma unroll
        for (int j = 0; j < VECS; ++j) {
            v[j] = __ldcs(&inv[(uint32_t)j * NTHREADS + tid]);
        }

        const uint32_t X  = base + tid * 4u;            // bits 11-12 == 0
        const uint32_t AX = X * POS_B + s2;              // 1 IMAD per thread
        const uint32_t RX = __funnelshift_l(X, X, 13);   // 1 SHF  per thread

        #pragma unroll
        for (int j = 0; j < VECS; ++j) {
            const uint32_t jo = (uint32_t)j * 2048u;     // compile-time
            hash_step_c(v[j].x, AX, RX, (jo + 0u) * POS_B,
                        ((uint32_t)j << 24) | (0u << 13), one, h2a);
            hash_step_c(v[j].y, AX, RX, (jo + 1u) * POS_B,
                        ((uint32_t)j << 24) | (1u << 13), one, h2b);
            hash_step_c(v[j].z, AX, RX, (jo + 2u) * POS_B,
                        ((uint32_t)j << 24) | (2u << 13), one, h2a);
            hash_step_c(v[j].w, AX, RX, (jo + 3u) * POS_B,
                        ((uint32_t)j << 24) | (3u << 13), one, h2b);
        }
    } else {
        // ragged tail tile: scalar guarded (not hit for n % TILE == 0)
        for (uint32_t w = tid; w < TILE_WORDS; w += NTHREADS) {
            uint32_t i = base + w;
            if (i < n) {
                uint32_t a2 = i * POS_B + s2;
                uint32_t r2 = __funnelshift_l(i, i, 13);
                h2a += fmix32(in[i] ^ a2 ^ r2);
            }
        }
    }

    uint32_t h2 = h2a + h2b;

    // warp reduction (wrapping uint32 adds)
    #pragma unroll
    for (int o = 16; o > 0; o >>= 1) {
        h2 += __shfl_down_sync(0xffffffffu, h2, o);
    }

    __shared__ uint32_t sh2[NWARPS];
    if ((tid & 31u) == 0u) sh2[tid >> 5] = h2;
    __syncthreads();

    if (tid == 0) {
        uint32_t b = 0u;
        #pragma unroll
        for (int w = 0; w < NWARPS; ++w) b += sh2[w];
        uint32_t nbytes = n * 4u;          // wrapping, matches (n*4) & 0xFFFFFFFF
        b = fmix32(b ^ nbytes);            // h2_final = low word of int64 hash
        // Output = int64 hash truncated to int32, value-cast to float32.
        out[tile] = (float)(int32_t)b;
    }
}

extern "C" void kernel_launch(void* const* d_in, const int* in_sizes, int n_in,
                              void* d_out, int out_size) {
    const uint32_t* in = (const uint32_t*)d_in[0];
    float* out = (float*)d_out;
    uint32_t n = (uint32_t)in_sizes[0];
    uint32_t n_tiles = (n + TILE_WORDS - 1) / TILE_WORDS;
    hash_tiles_kernel<<<n_tiles, NTHREADS>>>(in, out, n, 1u);
}